// round 1
// baseline (speedup 1.0000x reference)
#include <cuda_runtime.h>
#include <math.h>
#include <stdint.h>

// Problem constants (B, C, N, D, H, W) = (2, 8, 16384, 256, 64, 64)
#define BATCH 2
#define CH 8
#define NTOK 16384
#define DIM 256
#define IMH 64
#define IMW 64
#define TOKENS (BATCH * NTOK)   // 32768

// ---------------- scratch (device globals; no runtime allocation) ----------
__device__ float g_qn[TOKENS * DIM];      // LayerNorm output
__device__ float g_P[TOKENS * DIM];       // p = qn @ A + cA
__device__ float g_sbar[TOKENS * DIM];    // attention-weighted sampled features
__device__ float g_sumattn[TOKENS];       // 1.0 if any channel valid else 0.0
__device__ float g_A[DIM * DIM];          // A[f][e] = sum_d Wq[f,d] * Wk[e,d]
__device__ float g_B2[DIM * DIM];         // B2[e][g] = sum_d Wv[e,d] * Wo[d,g]
__device__ float g_cA[DIM];               // cA[e] = sum_d bq[d] * Wk[e,d]
__device__ float g_bvWo[DIM];             // (bv @ Wo)[g]

// ---------------- helpers ---------------------------------------------------
__device__ __forceinline__ float to_tf32(float x) {
    uint32_t u;
    asm("cvt.rna.tf32.f32 %0, %1;" : "=r"(u) : "f"(x));
    return __uint_as_float(u);
}

__device__ __forceinline__ void mma_tf32(float c[4], const float a[4], const float b[2]) {
    const uint32_t* A = reinterpret_cast<const uint32_t*>(a);
    const uint32_t* B = reinterpret_cast<const uint32_t*>(b);
    asm volatile(
        "mma.sync.aligned.m16n8k8.row.col.f32.tf32.tf32.f32 "
        "{%0,%1,%2,%3}, {%4,%5,%6,%7}, {%8,%9}, {%0,%1,%2,%3};\n"
        : "+f"(c[0]), "+f"(c[1]), "+f"(c[2]), "+f"(c[3])
        : "r"(A[0]), "r"(A[1]), "r"(A[2]), "r"(A[3]),
          "r"(B[0]), "r"(B[1]));
}

// ---------------- K0: precompute fused weight matrices ----------------------
// A[f,e] = sum_d Wq[f,d] * Wkv[e, d]          (Wk = Wkv[:, :D])
__global__ void precompute_A_kernel(const float* __restrict__ Wq,
                                    const float* __restrict__ Wkv) {
    int e = blockIdx.x * 16 + threadIdx.x;
    int f = blockIdx.y * 16 + threadIdx.y;
    float s = 0.f;
    #pragma unroll 8
    for (int d = 0; d < DIM; d++)
        s += Wq[f * DIM + d] * Wkv[e * 2 * DIM + d];
    g_A[f * DIM + e] = s;
}

// B2[e,g] = sum_d Wkv[e, D+d] * Wo[d,g]       (Wv = Wkv[:, D:])
__global__ void precompute_B2_kernel(const float* __restrict__ Wkv,
                                     const float* __restrict__ Wo) {
    int g = blockIdx.x * 16 + threadIdx.x;
    int e = blockIdx.y * 16 + threadIdx.y;
    float s = 0.f;
    #pragma unroll 8
    for (int d = 0; d < DIM; d++)
        s += Wkv[e * 2 * DIM + DIM + d] * Wo[d * DIM + g];
    g_B2[e * DIM + g] = s;
}

__global__ void precompute_vec_kernel(const float* __restrict__ bq,
                                      const float* __restrict__ Wkv,
                                      const float* __restrict__ bkv,
                                      const float* __restrict__ Wo) {
    int i = threadIdx.x;  // 256 threads
    float s = 0.f, t = 0.f;
    for (int d = 0; d < DIM; d++) {
        s += bq[d] * Wkv[i * 2 * DIM + d];
        t += bkv[DIM + d] * Wo[d * DIM + i];
    }
    g_cA[i] = s;
    g_bvWo[i] = t;
}

// ---------------- K1a: LayerNorm (1 warp / token) ----------------------------
__global__ __launch_bounds__(256) void ln_kernel(const float* __restrict__ q,
                                                 const float* __restrict__ gamma,
                                                 const float* __restrict__ beta) {
    int token = blockIdx.x * 8 + (threadIdx.x >> 5);
    int lane = threadIdx.x & 31;
    const float4* row = reinterpret_cast<const float4*>(q + (size_t)token * DIM);
    float4 x0 = row[lane];
    float4 x1 = row[lane + 32];

    float sum = x0.x + x0.y + x0.z + x0.w + x1.x + x1.y + x1.z + x1.w;
    float sq  = x0.x * x0.x + x0.y * x0.y + x0.z * x0.z + x0.w * x0.w
              + x1.x * x1.x + x1.y * x1.y + x1.z * x1.z + x1.w * x1.w;
    #pragma unroll
    for (int off = 16; off > 0; off >>= 1) {
        sum += __shfl_xor_sync(0xffffffffu, sum, off);
        sq  += __shfl_xor_sync(0xffffffffu, sq, off);
    }
    float mu = sum * (1.f / DIM);
    float var = sq * (1.f / DIM) - mu * mu;
    float rstd = rsqrtf(var + 1e-5f);

    const float4* g4 = reinterpret_cast<const float4*>(gamma);
    const float4* b4 = reinterpret_cast<const float4*>(beta);
    float4 ga = g4[lane], gb = g4[lane + 32];
    float4 ba = b4[lane], bb = b4[lane + 32];

    float4 o0, o1;
    o0.x = (x0.x - mu) * rstd * ga.x + ba.x;
    o0.y = (x0.y - mu) * rstd * ga.y + ba.y;
    o0.z = (x0.z - mu) * rstd * ga.z + ba.z;
    o0.w = (x0.w - mu) * rstd * ga.w + ba.w;
    o1.x = (x1.x - mu) * rstd * gb.x + bb.x;
    o1.y = (x1.y - mu) * rstd * gb.y + bb.y;
    o1.z = (x1.z - mu) * rstd * gb.z + bb.z;
    o1.w = (x1.w - mu) * rstd * gb.w + bb.w;

    float4* orow = reinterpret_cast<float4*>(g_qn + (size_t)token * DIM);
    orow[lane] = o0;
    orow[lane + 32] = o1;
}

// ---------------- tf32 GEMM: [32768,256] @ [256,256] -------------------------
// MODE 1:  g_P  = g_qn  @ g_A  + cA
// MODE 2:  Out  = resid + g_sbar @ g_B2 + sumattn*bvWo + bo
// CTA: 256 thr (8 warps), tile 128(M) x 64(N), K-chunk 32.
// Warp grid 4x2, warp tile 32x32 -> 2x4 m16n8k8 mma tiles.
template <int MODE>
__global__ __launch_bounds__(256) void gemm_tf32_kernel(float* __restrict__ OutParam,
                                                        const float* __restrict__ resid,
                                                        const float* __restrict__ bo) {
    const float* Ain = (MODE == 1) ? g_qn : g_sbar;
    const float* Wm  = (MODE == 1) ? g_A : g_B2;
    float* Out = (MODE == 1) ? g_P : OutParam;

    __shared__ float As[128 * 36];  // padded stride 36 -> conflict-free frag LDS
    __shared__ float Bs[32 * 72];   // padded stride 72 -> conflict-free frag LDS

    int tid = threadIdx.x;
    int warp = tid >> 5, lane = tid & 31;
    int wm = warp >> 1, wn = warp & 1;
    int grp = lane >> 2, tig = lane & 3;
    int m0 = blockIdx.x * 128;
    int n0 = blockIdx.y * 64;

    float acc[2][4][4];
    #pragma unroll
    for (int mt = 0; mt < 2; mt++)
        #pragma unroll
        for (int nt = 0; nt < 4; nt++)
            #pragma unroll
            for (int i = 0; i < 4; i++) acc[mt][nt][i] = 0.f;

    #pragma unroll 1
    for (int kc = 0; kc < DIM; kc += 32) {
        // stage A tile 128x32 (16 floats / thread)
        {
            int ar = tid >> 3;          // 0..31
            int ac = (tid & 7) * 4;     // 0..28
            #pragma unroll
            for (int rr = 0; rr < 4; rr++) {
                int row = ar + rr * 32;
                float4 v = *reinterpret_cast<const float4*>(
                    Ain + (size_t)(m0 + row) * DIM + kc + ac);
                As[row * 36 + ac + 0] = to_tf32(v.x);
                As[row * 36 + ac + 1] = to_tf32(v.y);
                As[row * 36 + ac + 2] = to_tf32(v.z);
                As[row * 36 + ac + 3] = to_tf32(v.w);
            }
        }
        // stage B tile 32x64 (8 floats / thread)
        {
            int bk = tid >> 4;           // 0..15
            int bn = (tid & 15) * 4;     // 0..60
            #pragma unroll
            for (int kk = 0; kk < 2; kk++) {
                int krow = bk + kk * 16;
                float4 v = *reinterpret_cast<const float4*>(
                    Wm + (size_t)(kc + krow) * DIM + n0 + bn);
                Bs[krow * 72 + bn + 0] = to_tf32(v.x);
                Bs[krow * 72 + bn + 1] = to_tf32(v.y);
                Bs[krow * 72 + bn + 2] = to_tf32(v.z);
                Bs[krow * 72 + bn + 3] = to_tf32(v.w);
            }
        }
        __syncthreads();

        #pragma unroll
        for (int ks = 0; ks < 4; ks++) {
            int k8 = ks * 8;
            float a[2][4], bf[4][2];
            #pragma unroll
            for (int mt = 0; mt < 2; mt++) {
                int row = wm * 32 + mt * 16 + grp;
                a[mt][0] = As[row * 36 + k8 + tig];
                a[mt][1] = As[(row + 8) * 36 + k8 + tig];
                a[mt][2] = As[row * 36 + k8 + tig + 4];
                a[mt][3] = As[(row + 8) * 36 + k8 + tig + 4];
            }
            #pragma unroll
            for (int nt = 0; nt < 4; nt++) {
                int col = wn * 32 + nt * 8 + grp;
                bf[nt][0] = Bs[(k8 + tig) * 72 + col];
                bf[nt][1] = Bs[(k8 + tig + 4) * 72 + col];
            }
            #pragma unroll
            for (int mt = 0; mt < 2; mt++)
                #pragma unroll
                for (int nt = 0; nt < 4; nt++)
                    mma_tf32(acc[mt][nt], a[mt], bf[nt]);
        }
        __syncthreads();
    }

    // epilogue
    #pragma unroll
    for (int mt = 0; mt < 2; mt++) {
        #pragma unroll
        for (int nt = 0; nt < 4; nt++) {
            #pragma unroll
            for (int half = 0; half < 2; half++) {
                int r = m0 + wm * 32 + mt * 16 + grp + half * 8;
                int col = n0 + wn * 32 + nt * 8 + tig * 2;
                float v0 = acc[mt][nt][half * 2 + 0];
                float v1 = acc[mt][nt][half * 2 + 1];
                if (MODE == 1) {
                    v0 += g_cA[col];
                    v1 += g_cA[col + 1];
                } else {
                    float sa = g_sumattn[r];
                    v0 += resid[(size_t)r * DIM + col]     + sa * g_bvWo[col]     + bo[col];
                    v1 += resid[(size_t)r * DIM + col + 1] + sa * g_bvWo[col + 1] + bo[col + 1];
                }
                *reinterpret_cast<float2*>(Out + (size_t)r * DIM + col) =
                    make_float2(v0, v1);
            }
        }
    }
}

// ---------------- K2: bilinear sample + score + softmax + sbar ---------------
// One warp per token. s_c kept in registers (8 channels x 8 floats/lane).
__global__ __launch_bounds__(256) void sample_attn_kernel(const float* __restrict__ feat,
                                                          const float* __restrict__ coords,
                                                          const int* __restrict__ vmask) {
    int token = blockIdx.x * 8 + (threadIdx.x >> 5);
    int lane = threadIdx.x & 31;
    int b = token >> 14;             // N = 16384
    int n = token & (NTOK - 1);

    const float4* prow = reinterpret_cast<const float4*>(g_P + (size_t)token * DIM);
    float4 p0 = prow[lane];
    float4 p1 = prow[lane + 32];

    float s[CH][8];
    float score[CH];
    unsigned validbits = 0;

    #pragma unroll
    for (int c = 0; c < CH; c++) {
        int bc = b * CH + c;
        int valid = vmask[bc * NTOK + n];
        float4 sa = make_float4(0.f, 0.f, 0.f, 0.f);
        float4 sb = make_float4(0.f, 0.f, 0.f, 0.f);
        float sc = -1e30f;
        if (valid) {
            validbits |= (1u << c);
            float2 xy = *reinterpret_cast<const float2*>(
                coords + ((size_t)bc * NTOK + n) * 2);
            float x = (xy.x + 1.f) * 0.5f * (float)(IMW - 1);
            float y = (xy.y + 1.f) * 0.5f * (float)(IMH - 1);
            float x0f = floorf(x), y0f = floorf(y);
            int x0 = (int)x0f, y0 = (int)y0f;
            float wx1 = x - x0f, wy1 = y - y0f;
            float ws[4] = {(1.f - wy1) * (1.f - wx1), (1.f - wy1) * wx1,
                           wy1 * (1.f - wx1),          wy1 * wx1};
            int xs[4] = {x0, x0 + 1, x0, x0 + 1};
            int ys[4] = {y0, y0, y0 + 1, y0 + 1};
            const float* fb = feat + (size_t)bc * (IMH * IMW * DIM);
            #pragma unroll
            for (int k = 0; k < 4; k++) {
                float w = ws[k];
                int xx = xs[k], yy = ys[k];
                if (w != 0.f && xx >= 0 && xx < IMW && yy >= 0 && yy < IMH) {
                    const float4* row = reinterpret_cast<const float4*>(
                        fb + ((size_t)yy * IMW + xx) * DIM);
                    float4 va = row[lane];
                    float4 vb = row[lane + 32];
                    sa.x += w * va.x; sa.y += w * va.y; sa.z += w * va.z; sa.w += w * va.w;
                    sb.x += w * vb.x; sb.y += w * vb.y; sb.z += w * vb.z; sb.w += w * vb.w;
                }
            }
            float d = sa.x * p0.x + sa.y * p0.y + sa.z * p0.z + sa.w * p0.w
                    + sb.x * p1.x + sb.y * p1.y + sb.z * p1.z + sb.w * p1.w;
            #pragma unroll
            for (int off = 16; off > 0; off >>= 1)
                d += __shfl_xor_sync(0xffffffffu, d, off);
            sc = d * (1.f / 16.f);   // 1/sqrt(D)
        }
        score[c] = sc;
        s[c][0] = sa.x; s[c][1] = sa.y; s[c][2] = sa.z; s[c][3] = sa.w;
        s[c][4] = sb.x; s[c][5] = sb.y; s[c][6] = sb.z; s[c][7] = sb.w;
    }

    float out[8];
    #pragma unroll
    for (int j = 0; j < 8; j++) out[j] = 0.f;
    float sumattn = 0.f;

    if (validbits) {
        float m = -1e30f;
        #pragma unroll
        for (int c = 0; c < CH; c++) m = fmaxf(m, score[c]);
        float wv[CH];
        float wsum = 0.f;
        #pragma unroll
        for (int c = 0; c < CH; c++) {
            float e = ((validbits >> c) & 1u) ? expf(score[c] - m) : 0.f;
            wv[c] = e;
            wsum += e;
        }
        float inv = 1.f / wsum;
        #pragma unroll
        for (int c = 0; c < CH; c++) {
            float a = wv[c] * inv;
            #pragma unroll
            for (int j = 0; j < 8; j++) out[j] += a * s[c][j];
        }
        sumattn = 1.f;
    }

    float4* srow = reinterpret_cast<float4*>(g_sbar + (size_t)token * DIM);
    srow[lane]      = make_float4(out[0], out[1], out[2], out[3]);
    srow[lane + 32] = make_float4(out[4], out[5], out[6], out[7]);
    if (lane == 0) g_sumattn[token] = sumattn;
}

// ---------------- launch -----------------------------------------------------
extern "C" void kernel_launch(void* const* d_in, const int* in_sizes, int n_in,
                              void* d_out, int out_size) {
    const float* queries = (const float*)d_in[0];
    const float* feat    = (const float*)d_in[1];
    const float* coords  = (const float*)d_in[2];
    const int*   vmask   = (const int*)d_in[3];
    const float* Wq      = (const float*)d_in[4];
    const float* bq      = (const float*)d_in[5];
    const float* Wkv     = (const float*)d_in[6];
    const float* bkv     = (const float*)d_in[7];
    const float* Wo      = (const float*)d_in[8];
    const float* bo      = (const float*)d_in[9];
    const float* gamma   = (const float*)d_in[10];
    const float* beta    = (const float*)d_in[11];
    float* out = (float*)d_out;

    dim3 tb16(16, 16);
    precompute_A_kernel<<<dim3(16, 16), tb16>>>(Wq, Wkv);
    precompute_B2_kernel<<<dim3(16, 16), tb16>>>(Wkv, Wo);
    precompute_vec_kernel<<<1, 256>>>(bq, Wkv, bkv, Wo);

    ln_kernel<<<TOKENS / 8, 256>>>(queries, gamma, beta);

    gemm_tf32_kernel<1><<<dim3(TOKENS / 128, DIM / 64), 256>>>(nullptr, nullptr, nullptr);

    sample_attn_kernel<<<TOKENS / 8, 256>>>(feat, coords, vmask);

    gemm_tf32_kernel<2><<<dim3(TOKENS / 128, DIM / 64), 256>>>(out, queries, bo);
}

// round 3
// speedup vs baseline: 1.1283x; 1.1283x over previous
#include <cuda_runtime.h>
#include <cuda_bf16.h>
#include <math.h>
#include <stdint.h>

// Problem constants (B, C, N, D, H, W) = (2, 8, 16384, 256, 64, 64)
#define BATCH 2
#define CH 8
#define NTOK 16384
#define DIM 256
#define IMH 64
#define IMW 64
#define TOKENS (BATCH * NTOK)                    // 32768
#define FEAT_U4 (BATCH * CH * IMH * IMW * 32)    // uint4 count: 16*4096*32 = 2097152

// ---------------- scratch (device globals; no runtime allocation) ----------
__device__ float g_P[TOKENS * DIM];       // p = LN(q) @ A + cA
__device__ float g_sbar[TOKENS * DIM];    // attention-weighted sampled features
__device__ float g_sumattn[TOKENS];       // 1.0 if any channel valid else 0.0
__device__ float2 g_stats[TOKENS];        // (mu, rstd) per token
__device__ float g_A[DIM * DIM];          // A[f][e] = sum_d Wq[f,d] * Wk[e,d]
__device__ float g_B2[DIM * DIM];         // B2[e][g] = sum_d Wv[e,d] * Wo[d,g]
__device__ float g_cA[DIM];               // cA[e] = sum_d bq[d] * Wk[e,d]
__device__ float g_bvWo[DIM];             // (bv @ Wo)[g]
__device__ uint4 g_featu4[FEAT_U4];       // image features packed as bf16 (8 per uint4)

// ---------------- helpers ---------------------------------------------------
__device__ __forceinline__ float to_tf32(float x) {
    uint32_t u;
    asm("cvt.rna.tf32.f32 %0, %1;" : "=r"(u) : "f"(x));
    return __uint_as_float(u);
}

__device__ __forceinline__ void mma_tf32(float c[4], const float a[4], const float b[2]) {
    const uint32_t* A = reinterpret_cast<const uint32_t*>(a);
    const uint32_t* B = reinterpret_cast<const uint32_t*>(b);
    asm volatile(
        "mma.sync.aligned.m16n8k8.row.col.f32.tf32.tf32.f32 "
        "{%0,%1,%2,%3}, {%4,%5,%6,%7}, {%8,%9}, {%0,%1,%2,%3};\n"
        : "+f"(c[0]), "+f"(c[1]), "+f"(c[2]), "+f"(c[3])
        : "r"(A[0]), "r"(A[1]), "r"(A[2]), "r"(A[3]),
          "r"(B[0]), "r"(B[1]));
}

__device__ __forceinline__ float2 bf2_to_f2(uint32_t u) {
    return make_float2(__uint_as_float(u << 16),
                       __uint_as_float(u & 0xffff0000u));
}

__device__ __forceinline__ uint32_t pack_bf2(float x, float y) {
    __nv_bfloat162 h = __floats2bfloat162_rn(x, y);
    return *reinterpret_cast<uint32_t*>(&h);
}

// ---------------- K0: precompute A and B2 (tiled GEMM, coalesced) -----------
// z=0:  A[f,e]  = sum_d Wq[f,d]  * Wkv[e,d]        (both K-major)
// z=1:  B2[e,g] = sum_d Wkv[e,256+d] * Wo[d,g]     (Wv K-major, Wo row-major over d)
// smem row stride 68 floats: 68 % 4 == 0 keeps every &UT[k][4*i] 16B-aligned
// for LDS.128 (stride 65 trapped with "misaligned address").
__global__ __launch_bounds__(256) void precompute_AB_kernel(const float* __restrict__ Wq,
                                                            const float* __restrict__ Wkv,
                                                            const float* __restrict__ Wo) {
    __shared__ float UT[64][68];  // UT[k][row]
    __shared__ float VT[64][68];  // VT[k][col]
    int z = blockIdx.z;
    int r0 = blockIdx.y * 64;
    int c0 = blockIdx.x * 64;
    int tid = threadIdx.x;
    int tr = tid >> 4, tc = tid & 15;

    float acc[4][4];
    #pragma unroll
    for (int i = 0; i < 4; i++)
        #pragma unroll
        for (int j = 0; j < 4; j++) acc[i][j] = 0.f;

    for (int kc = 0; kc < DIM; kc += 64) {
        #pragma unroll
        for (int t = tid; t < 1024; t += 256) {
            int row = t >> 4;
            int col = (t & 15) * 4;
            float4 u, v;
            if (z == 0) {
                u = *reinterpret_cast<const float4*>(Wq + (r0 + row) * DIM + kc + col);
                v = *reinterpret_cast<const float4*>(Wkv + (c0 + row) * 2 * DIM + kc + col);
                VT[col + 0][row] = v.x;
                VT[col + 1][row] = v.y;
                VT[col + 2][row] = v.z;
                VT[col + 3][row] = v.w;
            } else {
                u = *reinterpret_cast<const float4*>(Wkv + (r0 + row) * 2 * DIM + DIM + kc + col);
                v = *reinterpret_cast<const float4*>(Wo + (kc + row) * DIM + c0 + col);
                VT[row][col + 0] = v.x;
                VT[row][col + 1] = v.y;
                VT[row][col + 2] = v.z;
                VT[row][col + 3] = v.w;
            }
            UT[col + 0][row] = u.x;
            UT[col + 1][row] = u.y;
            UT[col + 2][row] = u.z;
            UT[col + 3][row] = u.w;
        }
        __syncthreads();
        #pragma unroll 8
        for (int k = 0; k < 64; k++) {
            float4 a = *reinterpret_cast<float4*>(&UT[k][tr * 4]);
            float4 b = *reinterpret_cast<float4*>(&VT[k][tc * 4]);
            float av[4] = {a.x, a.y, a.z, a.w};
            float bv[4] = {b.x, b.y, b.z, b.w};
            #pragma unroll
            for (int i = 0; i < 4; i++)
                #pragma unroll
                for (int j = 0; j < 4; j++) acc[i][j] += av[i] * bv[j];
        }
        __syncthreads();
    }

    float* Outm = z ? g_B2 : g_A;
    #pragma unroll
    for (int i = 0; i < 4; i++) {
        float4 o = make_float4(acc[i][0], acc[i][1], acc[i][2], acc[i][3]);
        *reinterpret_cast<float4*>(Outm + (size_t)(r0 + tr * 4 + i) * DIM + c0 + tc * 4) = o;
    }
}

// cA[i] = sum_d bq[d]*Wkv[i*512+d]   (warp per i, coalesced over d)
// bvWo[i] = sum_d bkv[256+d]*Wo[d*256+i]  (thread per i, coalesced over i)
__global__ __launch_bounds__(256) void precompute_vec_kernel(const float* __restrict__ bq,
                                                             const float* __restrict__ Wkv,
                                                             const float* __restrict__ bkv,
                                                             const float* __restrict__ Wo) {
    int tid = threadIdx.x;
    int lane = tid & 31, warp = tid >> 5;

    float4 q0 = *reinterpret_cast<const float4*>(bq + lane * 8);
    float4 q1 = *reinterpret_cast<const float4*>(bq + lane * 8 + 4);
    for (int i = warp; i < DIM; i += 8) {
        float4 w0 = *reinterpret_cast<const float4*>(Wkv + (size_t)i * 2 * DIM + lane * 8);
        float4 w1 = *reinterpret_cast<const float4*>(Wkv + (size_t)i * 2 * DIM + lane * 8 + 4);
        float s = w0.x * q0.x + w0.y * q0.y + w0.z * q0.z + w0.w * q0.w
                + w1.x * q1.x + w1.y * q1.y + w1.z * q1.z + w1.w * q1.w;
        #pragma unroll
        for (int off = 16; off > 0; off >>= 1)
            s += __shfl_xor_sync(0xffffffffu, s, off);
        if (lane == 0) g_cA[i] = s;
    }

    float t = 0.f;
    for (int d = 0; d < DIM; d++)
        t += bkv[DIM + d] * Wo[d * DIM + tid];
    g_bvWo[tid] = t;
}

// ---------------- K0b: convert image features to packed bf16 ----------------
__global__ __launch_bounds__(256) void convert_feat_kernel(const float* __restrict__ feat) {
    int i = blockIdx.x * 256 + threadIdx.x;  // uint4 index (8 floats)
    const float4* f4 = reinterpret_cast<const float4*>(feat);
    float4 a = f4[2 * i];
    float4 b = f4[2 * i + 1];
    uint4 o;
    o.x = pack_bf2(a.x, a.y);
    o.y = pack_bf2(a.z, a.w);
    o.z = pack_bf2(b.x, b.y);
    o.w = pack_bf2(b.z, b.w);
    g_featu4[i] = o;
}

// ---------------- K1: LayerNorm statistics (1 warp / token) ------------------
__global__ __launch_bounds__(256) void ln_stats_kernel(const float* __restrict__ q) {
    int token = blockIdx.x * 8 + (threadIdx.x >> 5);
    int lane = threadIdx.x & 31;
    const float4* row = reinterpret_cast<const float4*>(q + (size_t)token * DIM);
    float4 x0 = row[lane];
    float4 x1 = row[lane + 32];

    float sum = x0.x + x0.y + x0.z + x0.w + x1.x + x1.y + x1.z + x1.w;
    float sq  = x0.x * x0.x + x0.y * x0.y + x0.z * x0.z + x0.w * x0.w
              + x1.x * x1.x + x1.y * x1.y + x1.z * x1.z + x1.w * x1.w;
    #pragma unroll
    for (int off = 16; off > 0; off >>= 1) {
        sum += __shfl_xor_sync(0xffffffffu, sum, off);
        sq  += __shfl_xor_sync(0xffffffffu, sq, off);
    }
    float mu = sum * (1.f / DIM);
    float var = sq * (1.f / DIM) - mu * mu;
    float rstd = rsqrtf(var + 1e-5f);
    if (lane == 0) g_stats[token] = make_float2(mu, rstd);
}

// ---------------- tf32 GEMM: [32768,256] @ [256,256] -------------------------
// MODE 1:  g_P  = LN(queries) @ g_A  + cA      (LN applied during A-staging)
// MODE 2:  Out  = resid + g_sbar @ g_B2 + sumattn*bvWo + bo
template <int MODE>
__global__ __launch_bounds__(256) void gemm_tf32_kernel(float* __restrict__ OutParam,
                                                        const float* __restrict__ AinParam,
                                                        const float* __restrict__ bo,
                                                        const float* __restrict__ gamma,
                                                        const float* __restrict__ beta,
                                                        const float* __restrict__ resid) {
    const float* Ain = (MODE == 1) ? AinParam : g_sbar;
    const float* Wm  = (MODE == 1) ? g_A : g_B2;
    float* Out = (MODE == 1) ? g_P : OutParam;

    __shared__ float As[128 * 36];
    __shared__ float Bs[32 * 72];

    int tid = threadIdx.x;
    int warp = tid >> 5, lane = tid & 31;
    int wm = warp >> 1, wn = warp & 1;
    int grp = lane >> 2, tig = lane & 3;
    int m0 = blockIdx.x * 128;
    int n0 = blockIdx.y * 64;

    float acc[2][4][4];
    #pragma unroll
    for (int mt = 0; mt < 2; mt++)
        #pragma unroll
        for (int nt = 0; nt < 4; nt++)
            #pragma unroll
            for (int i = 0; i < 4; i++) acc[mt][nt][i] = 0.f;

    #pragma unroll 1
    for (int kc = 0; kc < DIM; kc += 32) {
        // stage A tile 128x32
        {
            int ar = tid >> 3;
            int ac = (tid & 7) * 4;
            float4 gm, bt;
            if (MODE == 1) {
                gm = *reinterpret_cast<const float4*>(gamma + kc + ac);
                bt = *reinterpret_cast<const float4*>(beta + kc + ac);
            }
            #pragma unroll
            for (int rr = 0; rr < 4; rr++) {
                int row = ar + rr * 32;
                float4 v = *reinterpret_cast<const float4*>(
                    Ain + (size_t)(m0 + row) * DIM + kc + ac);
                if (MODE == 1) {
                    float2 st = g_stats[m0 + row];
                    v.x = (v.x - st.x) * st.y * gm.x + bt.x;
                    v.y = (v.y - st.x) * st.y * gm.y + bt.y;
                    v.z = (v.z - st.x) * st.y * gm.z + bt.z;
                    v.w = (v.w - st.x) * st.y * gm.w + bt.w;
                }
                As[row * 36 + ac + 0] = to_tf32(v.x);
                As[row * 36 + ac + 1] = to_tf32(v.y);
                As[row * 36 + ac + 2] = to_tf32(v.z);
                As[row * 36 + ac + 3] = to_tf32(v.w);
            }
        }
        // stage B tile 32x64
        {
            int bk = tid >> 4;
            int bn = (tid & 15) * 4;
            #pragma unroll
            for (int kk = 0; kk < 2; kk++) {
                int krow = bk + kk * 16;
                float4 v = *reinterpret_cast<const float4*>(
                    Wm + (size_t)(kc + krow) * DIM + n0 + bn);
                Bs[krow * 72 + bn + 0] = to_tf32(v.x);
                Bs[krow * 72 + bn + 1] = to_tf32(v.y);
                Bs[krow * 72 + bn + 2] = to_tf32(v.z);
                Bs[krow * 72 + bn + 3] = to_tf32(v.w);
            }
        }
        __syncthreads();

        #pragma unroll
        for (int ks = 0; ks < 4; ks++) {
            int k8 = ks * 8;
            float a[2][4], bf[4][2];
            #pragma unroll
            for (int mt = 0; mt < 2; mt++) {
                int row = wm * 32 + mt * 16 + grp;
                a[mt][0] = As[row * 36 + k8 + tig];
                a[mt][1] = As[(row + 8) * 36 + k8 + tig];
                a[mt][2] = As[row * 36 + k8 + tig + 4];
                a[mt][3] = As[(row + 8) * 36 + k8 + tig + 4];
            }
            #pragma unroll
            for (int nt = 0; nt < 4; nt++) {
                int col = wn * 32 + nt * 8 + grp;
                bf[nt][0] = Bs[(k8 + tig) * 72 + col];
                bf[nt][1] = Bs[(k8 + tig + 4) * 72 + col];
            }
            #pragma unroll
            for (int mt = 0; mt < 2; mt++)
                #pragma unroll
                for (int nt = 0; nt < 4; nt++)
                    mma_tf32(acc[mt][nt], a[mt], bf[nt]);
        }
        __syncthreads();
    }

    // epilogue
    #pragma unroll
    for (int mt = 0; mt < 2; mt++) {
        #pragma unroll
        for (int nt = 0; nt < 4; nt++) {
            #pragma unroll
            for (int half = 0; half < 2; half++) {
                int r = m0 + wm * 32 + mt * 16 + grp + half * 8;
                int col = n0 + wn * 32 + nt * 8 + tig * 2;
                float v0 = acc[mt][nt][half * 2 + 0];
                float v1 = acc[mt][nt][half * 2 + 1];
                if (MODE == 1) {
                    v0 += g_cA[col];
                    v1 += g_cA[col + 1];
                } else {
                    float sa = g_sumattn[r];
                    v0 += resid[(size_t)r * DIM + col]     + sa * g_bvWo[col]     + bo[col];
                    v1 += resid[(size_t)r * DIM + col + 1] + sa * g_bvWo[col + 1] + bo[col + 1];
                }
                *reinterpret_cast<float2*>(Out + (size_t)r * DIM + col) =
                    make_float2(v0, v1);
            }
        }
    }
}

// ---------------- K2: bilinear sample + score + softmax + sbar ---------------
// One warp per token. Features gathered as packed bf16 (one LDG.128 per corner).
__global__ __launch_bounds__(256) void sample_attn_kernel(const float* __restrict__ coords,
                                                          const int* __restrict__ vmask) {
    int token = blockIdx.x * 8 + (threadIdx.x >> 5);
    int lane = threadIdx.x & 31;
    int b = token >> 14;             // N = 16384
    int n = token & (NTOK - 1);

    const float4* prow = reinterpret_cast<const float4*>(g_P + (size_t)token * DIM);
    float4 p0 = prow[2 * lane];       // dims [8*lane, 8*lane+4)
    float4 p1 = prow[2 * lane + 1];   // dims [8*lane+4, 8*lane+8)

    float s[CH][8];
    float score[CH];
    unsigned validbits = 0;

    #pragma unroll
    for (int c = 0; c < CH; c++) {
        int bc = b * CH + c;
        int valid = vmask[bc * NTOK + n];
        float a0 = 0.f, a1 = 0.f, a2 = 0.f, a3 = 0.f;
        float a4 = 0.f, a5 = 0.f, a6 = 0.f, a7 = 0.f;
        float sc = -1e30f;
        if (valid) {
            validbits |= (1u << c);
            float2 xy = *reinterpret_cast<const float2*>(
                coords + ((size_t)bc * NTOK + n) * 2);
            float x = (xy.x + 1.f) * 0.5f * (float)(IMW - 1);
            float y = (xy.y + 1.f) * 0.5f * (float)(IMH - 1);
            float x0f = floorf(x), y0f = floorf(y);
            int x0 = (int)x0f, y0 = (int)y0f;
            float wx1 = x - x0f, wy1 = y - y0f;
            float ws[4] = {(1.f - wy1) * (1.f - wx1), (1.f - wy1) * wx1,
                           wy1 * (1.f - wx1),          wy1 * wx1};
            int xs[4] = {x0, x0 + 1, x0, x0 + 1};
            int ys[4] = {y0, y0, y0 + 1, y0 + 1};
            const uint4* fb = g_featu4 + (size_t)bc * (IMH * IMW * 32);
            #pragma unroll
            for (int k = 0; k < 4; k++) {
                float w = ws[k];
                int xx = xs[k], yy = ys[k];
                if (w != 0.f && xx >= 0 && xx < IMW && yy >= 0 && yy < IMH) {
                    uint4 v = fb[(yy * IMW + xx) * 32 + lane];
                    float2 e0 = bf2_to_f2(v.x);
                    float2 e1 = bf2_to_f2(v.y);
                    float2 e2 = bf2_to_f2(v.z);
                    float2 e3 = bf2_to_f2(v.w);
                    a0 += w * e0.x; a1 += w * e0.y;
                    a2 += w * e1.x; a3 += w * e1.y;
                    a4 += w * e2.x; a5 += w * e2.y;
                    a6 += w * e3.x; a7 += w * e3.y;
                }
            }
            float d = a0 * p0.x + a1 * p0.y + a2 * p0.z + a3 * p0.w
                    + a4 * p1.x + a5 * p1.y + a6 * p1.z + a7 * p1.w;
            #pragma unroll
            for (int off = 16; off > 0; off >>= 1)
                d += __shfl_xor_sync(0xffffffffu, d, off);
            sc = d * (1.f / 16.f);   // 1/sqrt(256)
        }
        score[c] = sc;
        s[c][0] = a0; s[c][1] = a1; s[c][2] = a2; s[c][3] = a3;
        s[c][4] = a4; s[c][5] = a5; s[c][6] = a6; s[c][7] = a7;
    }

    float out[8];
    #pragma unroll
    for (int j = 0; j < 8; j++) out[j] = 0.f;
    float sumattn = 0.f;

    if (validbits) {
        float m = -1e30f;
        #pragma unroll
        for (int c = 0; c < CH; c++) m = fmaxf(m, score[c]);
        float wv[CH];
        float wsum = 0.f;
        #pragma unroll
        for (int c = 0; c < CH; c++) {
            float e = ((validbits >> c) & 1u) ? expf(score[c] - m) : 0.f;
            wv[c] = e;
            wsum += e;
        }
        float inv = 1.f / wsum;
        #pragma unroll
        for (int c = 0; c < CH; c++) {
            float a = wv[c] * inv;
            #pragma unroll
            for (int j = 0; j < 8; j++) out[j] += a * s[c][j];
        }
        sumattn = 1.f;
    }

    float4* srow = reinterpret_cast<float4*>(g_sbar + (size_t)token * DIM);
    srow[2 * lane]     = make_float4(out[0], out[1], out[2], out[3]);
    srow[2 * lane + 1] = make_float4(out[4], out[5], out[6], out[7]);
    if (lane == 0) g_sumattn[token] = sumattn;
}

// ---------------- launch -----------------------------------------------------
extern "C" void kernel_launch(void* const* d_in, const int* in_sizes, int n_in,
                              void* d_out, int out_size) {
    const float* queries = (const float*)d_in[0];
    const float* feat    = (const float*)d_in[1];
    const float* coords  = (const float*)d_in[2];
    const int*   vmask   = (const int*)d_in[3];
    const float* Wq      = (const float*)d_in[4];
    const float* bq      = (const float*)d_in[5];
    const float* Wkv     = (const float*)d_in[6];
    const float* bkv     = (const float*)d_in[7];
    const float* Wo      = (const float*)d_in[8];
    const float* bo      = (const float*)d_in[9];
    const float* gamma   = (const float*)d_in[10];
    const float* beta    = (const float*)d_in[11];
    float* out = (float*)d_out;

    precompute_AB_kernel<<<dim3(4, 4, 2), 256>>>(Wq, Wkv, Wo);
    precompute_vec_kernel<<<1, 256>>>(bq, Wkv, bkv, Wo);
    convert_feat_kernel<<<FEAT_U4 / 256, 256>>>(feat);
    ln_stats_kernel<<<TOKENS / 8, 256>>>(queries);

    gemm_tf32_kernel<1><<<dim3(TOKENS / 128, DIM / 64), 256>>>(
        nullptr, queries, nullptr, gamma, beta, nullptr);

    sample_attn_kernel<<<TOKENS / 8, 256>>>(coords, vmask);

    gemm_tf32_kernel<2><<<dim3(TOKENS / 128, DIM / 64), 256>>>(
        out, nullptr, bo, nullptr, nullptr, queries);
}

// round 4
// speedup vs baseline: 1.1716x; 1.0384x over previous
#include <cuda_runtime.h>
#include <cuda_fp16.h>
#include <math.h>
#include <stdint.h>

// Problem constants (B, C, N, D, H, W) = (2, 8, 16384, 256, 64, 64)
#define BATCH 2
#define CH 8
#define NTOK 16384
#define DIM 256
#define IMH 64
#define IMW 64
#define TOKENS (BATCH * NTOK)                    // 32768
#define FEAT_U4 (BATCH * CH * IMH * IMW * 32)    // uint4 count (8 fp16 each)

// ---------------- scratch (device globals; no runtime allocation) ----------
__device__ float g_qn[TOKENS * DIM];      // LN output, tf32-rounded
__device__ float g_P[TOKENS * DIM];       // p = qn @ A + cA
__device__ float g_sbar[TOKENS * DIM];    // attn-weighted sampled feats, tf32-rounded
__device__ float g_sumattn[TOKENS];       // 1.0 if any channel valid else 0.0
__device__ float g_A[DIM * DIM];          // tf32-rounded
__device__ float g_B2[DIM * DIM];         // tf32-rounded
__device__ float g_cA[DIM];
__device__ float g_bvWo[DIM];
__device__ uint4 g_featu4[FEAT_U4];       // image features packed as fp16 (8 per uint4)

// ---------------- helpers ---------------------------------------------------
__device__ __forceinline__ float to_tf32(float x) {
    uint32_t u;
    asm("cvt.rna.tf32.f32 %0, %1;" : "=r"(u) : "f"(x));
    return __uint_as_float(u);
}

__device__ __forceinline__ void mma_tf32(float c[4], const float a[4], const float b[2]) {
    const uint32_t* A = reinterpret_cast<const uint32_t*>(a);
    const uint32_t* B = reinterpret_cast<const uint32_t*>(b);
    asm volatile(
        "mma.sync.aligned.m16n8k8.row.col.f32.tf32.tf32.f32 "
        "{%0,%1,%2,%3}, {%4,%5,%6,%7}, {%8,%9}, {%0,%1,%2,%3};\n"
        : "+f"(c[0]), "+f"(c[1]), "+f"(c[2]), "+f"(c[3])
        : "r"(A[0]), "r"(A[1]), "r"(A[2]), "r"(A[3]),
          "r"(B[0]), "r"(B[1]));
}

__device__ __forceinline__ void cp_async16(void* smem, const void* gmem) {
    uint32_t s = (uint32_t)__cvta_generic_to_shared(smem);
    asm volatile("cp.async.ca.shared.global [%0], [%1], 16;\n" :: "r"(s), "l"(gmem));
}
__device__ __forceinline__ void cp_commit() {
    asm volatile("cp.async.commit_group;\n");
}
template <int N>
__device__ __forceinline__ void cp_wait() {
    asm volatile("cp.async.wait_group %0;\n" :: "n"(N));
}

__device__ __forceinline__ float2 h2_to_f2(uint32_t u) {
    __half2 h = *reinterpret_cast<__half2*>(&u);
    return __half22float2(h);
}
__device__ __forceinline__ uint32_t pack_h2(float x, float y) {
    __half2 h = __floats2half2_rn(x, y);
    return *reinterpret_cast<uint32_t*>(&h);
}

// ---------------- K0: precompute A and B2 (tiled GEMM, coalesced) -----------
__global__ __launch_bounds__(256) void precompute_AB_kernel(const float* __restrict__ Wq,
                                                            const float* __restrict__ Wkv,
                                                            const float* __restrict__ Wo) {
    __shared__ float UT[64][68];
    __shared__ float VT[64][68];
    int z = blockIdx.z;
    int r0 = blockIdx.y * 64;
    int c0 = blockIdx.x * 64;
    int tid = threadIdx.x;
    int tr = tid >> 4, tc = tid & 15;

    float acc[4][4];
    #pragma unroll
    for (int i = 0; i < 4; i++)
        #pragma unroll
        for (int j = 0; j < 4; j++) acc[i][j] = 0.f;

    for (int kc = 0; kc < DIM; kc += 64) {
        #pragma unroll
        for (int t = tid; t < 1024; t += 256) {
            int row = t >> 4;
            int col = (t & 15) * 4;
            float4 u, v;
            if (z == 0) {
                u = *reinterpret_cast<const float4*>(Wq + (r0 + row) * DIM + kc + col);
                v = *reinterpret_cast<const float4*>(Wkv + (c0 + row) * 2 * DIM + kc + col);
                VT[col + 0][row] = v.x;
                VT[col + 1][row] = v.y;
                VT[col + 2][row] = v.z;
                VT[col + 3][row] = v.w;
            } else {
                u = *reinterpret_cast<const float4*>(Wkv + (r0 + row) * 2 * DIM + DIM + kc + col);
                v = *reinterpret_cast<const float4*>(Wo + (kc + row) * DIM + c0 + col);
                VT[row][col + 0] = v.x;
                VT[row][col + 1] = v.y;
                VT[row][col + 2] = v.z;
                VT[row][col + 3] = v.w;
            }
            UT[col + 0][row] = u.x;
            UT[col + 1][row] = u.y;
            UT[col + 2][row] = u.z;
            UT[col + 3][row] = u.w;
        }
        __syncthreads();
        #pragma unroll 8
        for (int k = 0; k < 64; k++) {
            float4 a = *reinterpret_cast<float4*>(&UT[k][tr * 4]);
            float4 b = *reinterpret_cast<float4*>(&VT[k][tc * 4]);
            float av[4] = {a.x, a.y, a.z, a.w};
            float bv[4] = {b.x, b.y, b.z, b.w};
            #pragma unroll
            for (int i = 0; i < 4; i++)
                #pragma unroll
                for (int j = 0; j < 4; j++) acc[i][j] += av[i] * bv[j];
        }
        __syncthreads();
    }

    float* Outm = z ? g_B2 : g_A;
    #pragma unroll
    for (int i = 0; i < 4; i++) {
        float4 o = make_float4(to_tf32(acc[i][0]), to_tf32(acc[i][1]),
                               to_tf32(acc[i][2]), to_tf32(acc[i][3]));
        *reinterpret_cast<float4*>(Outm + (size_t)(r0 + tr * 4 + i) * DIM + c0 + tc * 4) = o;
    }
}

__global__ __launch_bounds__(256) void precompute_vec_kernel(const float* __restrict__ bq,
                                                             const float* __restrict__ Wkv,
                                                             const float* __restrict__ bkv,
                                                             const float* __restrict__ Wo) {
    int tid = threadIdx.x;
    int lane = tid & 31, warp = tid >> 5;

    float4 q0 = *reinterpret_cast<const float4*>(bq + lane * 8);
    float4 q1 = *reinterpret_cast<const float4*>(bq + lane * 8 + 4);
    for (int i = warp; i < DIM; i += 8) {
        float4 w0 = *reinterpret_cast<const float4*>(Wkv + (size_t)i * 2 * DIM + lane * 8);
        float4 w1 = *reinterpret_cast<const float4*>(Wkv + (size_t)i * 2 * DIM + lane * 8 + 4);
        float s = w0.x * q0.x + w0.y * q0.y + w0.z * q0.z + w0.w * q0.w
                + w1.x * q1.x + w1.y * q1.y + w1.z * q1.z + w1.w * q1.w;
        #pragma unroll
        for (int off = 16; off > 0; off >>= 1)
            s += __shfl_xor_sync(0xffffffffu, s, off);
        if (lane == 0) g_cA[i] = s;
    }

    float t = 0.f;
    for (int d = 0; d < DIM; d++)
        t += bkv[DIM + d] * Wo[d * DIM + tid];
    g_bvWo[tid] = t;
}

// ---------------- K0b: convert image features to packed fp16 ----------------
__global__ __launch_bounds__(256) void convert_feat_kernel(const float* __restrict__ feat) {
    int i = blockIdx.x * 256 + threadIdx.x;
    const float4* f4 = reinterpret_cast<const float4*>(feat);
    float4 a = f4[2 * i];
    float4 b = f4[2 * i + 1];
    uint4 o;
    o.x = pack_h2(a.x, a.y);
    o.y = pack_h2(a.z, a.w);
    o.z = pack_h2(b.x, b.y);
    o.w = pack_h2(b.z, b.w);
    g_featu4[i] = o;
}

// ---------------- K1: LayerNorm -> tf32-rounded qn ---------------------------
__global__ __launch_bounds__(256) void ln_kernel(const float* __restrict__ q,
                                                 const float* __restrict__ gamma,
                                                 const float* __restrict__ beta) {
    int token = blockIdx.x * 8 + (threadIdx.x >> 5);
    int lane = threadIdx.x & 31;
    const float4* row = reinterpret_cast<const float4*>(q + (size_t)token * DIM);
    float4 x0 = row[lane];
    float4 x1 = row[lane + 32];

    float sum = x0.x + x0.y + x0.z + x0.w + x1.x + x1.y + x1.z + x1.w;
    float sq  = x0.x * x0.x + x0.y * x0.y + x0.z * x0.z + x0.w * x0.w
              + x1.x * x1.x + x1.y * x1.y + x1.z * x1.z + x1.w * x1.w;
    #pragma unroll
    for (int off = 16; off > 0; off >>= 1) {
        sum += __shfl_xor_sync(0xffffffffu, sum, off);
        sq  += __shfl_xor_sync(0xffffffffu, sq, off);
    }
    float mu = sum * (1.f / DIM);
    float var = sq * (1.f / DIM) - mu * mu;
    float rstd = rsqrtf(var + 1e-5f);

    const float4* g4 = reinterpret_cast<const float4*>(gamma);
    const float4* b4 = reinterpret_cast<const float4*>(beta);
    float4 ga = g4[lane], gb = g4[lane + 32];
    float4 ba = b4[lane], bb = b4[lane + 32];

    float4 o0, o1;
    o0.x = to_tf32((x0.x - mu) * rstd * ga.x + ba.x);
    o0.y = to_tf32((x0.y - mu) * rstd * ga.y + ba.y);
    o0.z = to_tf32((x0.z - mu) * rstd * ga.z + ba.z);
    o0.w = to_tf32((x0.w - mu) * rstd * ga.w + ba.w);
    o1.x = to_tf32((x1.x - mu) * rstd * gb.x + bb.x);
    o1.y = to_tf32((x1.y - mu) * rstd * gb.y + bb.y);
    o1.z = to_tf32((x1.z - mu) * rstd * gb.z + bb.z);
    o1.w = to_tf32((x1.w - mu) * rstd * gb.w + bb.w);

    float4* orow = reinterpret_cast<float4*>(g_qn + (size_t)token * DIM);
    orow[lane] = o0;
    orow[lane + 32] = o1;
}

// ---------------- tf32 GEMM with cp.async double buffering -------------------
// MODE 1:  g_P  = g_qn  @ g_A  + cA
// MODE 2:  Out  = resid + g_sbar @ g_B2 + sumattn*bvWo + bo
// Inputs are pre-rounded to tf32; staging is a pure LDGSTS copy.
template <int MODE>
__global__ __launch_bounds__(256) void gemm_tf32_kernel(float* __restrict__ OutParam,
                                                        const float* __restrict__ bo,
                                                        const float* __restrict__ resid) {
    const float* Ain = (MODE == 1) ? g_qn : g_sbar;
    const float* Wm  = (MODE == 1) ? g_A : g_B2;
    float* Out = (MODE == 1) ? g_P : OutParam;

    __shared__ float As[2][128 * 36];
    __shared__ float Bs[2][32 * 72];

    int tid = threadIdx.x;
    int warp = tid >> 5, lane = tid & 31;
    int wm = warp >> 1, wn = warp & 1;
    int grp = lane >> 2, tig = lane & 3;
    int m0 = blockIdx.x * 128;
    int n0 = blockIdx.y * 64;

    int ar = tid >> 3;           // A stage: rows ar+32*rr, cols ac..ac+3
    int ac = (tid & 7) * 4;
    int bk = tid >> 4;           // B stage: rows bk+16*kk, cols bn..bn+3
    int bn = (tid & 15) * 4;

    float acc[2][4][4];
    #pragma unroll
    for (int mt = 0; mt < 2; mt++)
        #pragma unroll
        for (int nt = 0; nt < 4; nt++)
            #pragma unroll
            for (int i = 0; i < 4; i++) acc[mt][nt][i] = 0.f;

    auto stage = [&](int kc, int buf) {
        #pragma unroll
        for (int rr = 0; rr < 4; rr++) {
            int row = ar + rr * 32;
            cp_async16(&As[buf][row * 36 + ac],
                       Ain + (size_t)(m0 + row) * DIM + kc + ac);
        }
        #pragma unroll
        for (int kk = 0; kk < 2; kk++) {
            int krow = bk + kk * 16;
            cp_async16(&Bs[buf][krow * 72 + bn],
                       Wm + (size_t)(kc + krow) * DIM + n0 + bn);
        }
        cp_commit();
    };

    stage(0, 0);

    #pragma unroll 1
    for (int c = 0; c < 8; c++) {
        int buf = c & 1;
        if (c < 7) stage((c + 1) * 32, buf ^ 1);
        if (c < 7) cp_wait<1>(); else cp_wait<0>();
        __syncthreads();

        #pragma unroll
        for (int ks = 0; ks < 4; ks++) {
            int k8 = ks * 8;
            float a[2][4], bf[4][2];
            #pragma unroll
            for (int mt = 0; mt < 2; mt++) {
                int row = wm * 32 + mt * 16 + grp;
                a[mt][0] = As[buf][row * 36 + k8 + tig];
                a[mt][1] = As[buf][(row + 8) * 36 + k8 + tig];
                a[mt][2] = As[buf][row * 36 + k8 + tig + 4];
                a[mt][3] = As[buf][(row + 8) * 36 + k8 + tig + 4];
            }
            #pragma unroll
            for (int nt = 0; nt < 4; nt++) {
                int col = wn * 32 + nt * 8 + grp;
                bf[nt][0] = Bs[buf][(k8 + tig) * 72 + col];
                bf[nt][1] = Bs[buf][(k8 + tig + 4) * 72 + col];
            }
            #pragma unroll
            for (int mt = 0; mt < 2; mt++)
                #pragma unroll
                for (int nt = 0; nt < 4; nt++)
                    mma_tf32(acc[mt][nt], a[mt], bf[nt]);
        }
        __syncthreads();
    }

    // epilogue
    #pragma unroll
    for (int mt = 0; mt < 2; mt++) {
        #pragma unroll
        for (int nt = 0; nt < 4; nt++) {
            #pragma unroll
            for (int half = 0; half < 2; half++) {
                int r = m0 + wm * 32 + mt * 16 + grp + half * 8;
                int col = n0 + wn * 32 + nt * 8 + tig * 2;
                float v0 = acc[mt][nt][half * 2 + 0];
                float v1 = acc[mt][nt][half * 2 + 1];
                if (MODE == 1) {
                    v0 += g_cA[col];
                    v1 += g_cA[col + 1];
                } else {
                    float sa = g_sumattn[r];
                    v0 += resid[(size_t)r * DIM + col]     + sa * g_bvWo[col]     + bo[col];
                    v1 += resid[(size_t)r * DIM + col + 1] + sa * g_bvWo[col + 1] + bo[col + 1];
                }
                *reinterpret_cast<float2*>(Out + (size_t)r * DIM + col) =
                    make_float2(v0, v1);
            }
        }
    }
}

// ---------------- K2: bilinear sample + score + softmax + sbar ---------------
__global__ __launch_bounds__(256) void sample_attn_kernel(const float* __restrict__ coords,
                                                          const int* __restrict__ vmask) {
    int token = blockIdx.x * 8 + (threadIdx.x >> 5);
    int lane = threadIdx.x & 31;
    int b = token >> 14;
    int n = token & (NTOK - 1);

    const float4* prow = reinterpret_cast<const float4*>(g_P + (size_t)token * DIM);
    float4 p0 = prow[2 * lane];
    float4 p1 = prow[2 * lane + 1];

    float s[CH][8];
    float score[CH];
    unsigned validbits = 0;

    #pragma unroll
    for (int c = 0; c < CH; c++) {
        int bc = b * CH + c;
        int valid = vmask[bc * NTOK + n];
        float a0 = 0.f, a1 = 0.f, a2 = 0.f, a3 = 0.f;
        float a4 = 0.f, a5 = 0.f, a6 = 0.f, a7 = 0.f;
        float sc = -1e30f;
        if (valid) {
            validbits |= (1u << c);
            float2 xy = *reinterpret_cast<const float2*>(
                coords + ((size_t)bc * NTOK + n) * 2);
            float x = (xy.x + 1.f) * 0.5f * (float)(IMW - 1);
            float y = (xy.y + 1.f) * 0.5f * (float)(IMH - 1);
            float x0f = floorf(x), y0f = floorf(y);
            int x0 = (int)x0f, y0 = (int)y0f;
            float wx1 = x - x0f, wy1 = y - y0f;
            float ws[4] = {(1.f - wy1) * (1.f - wx1), (1.f - wy1) * wx1,
                           wy1 * (1.f - wx1),          wy1 * wx1};
            int xs[4] = {x0, x0 + 1, x0, x0 + 1};
            int ys[4] = {y0, y0, y0 + 1, y0 + 1};
            const uint4* fb = g_featu4 + (size_t)bc * (IMH * IMW * 32);
            #pragma unroll
            for (int k = 0; k < 4; k++) {
                float w = ws[k];
                int xx = xs[k], yy = ys[k];
                if (w != 0.f && xx >= 0 && xx < IMW && yy >= 0 && yy < IMH) {
                    uint4 v = fb[(yy * IMW + xx) * 32 + lane];
                    float2 e0 = h2_to_f2(v.x);
                    float2 e1 = h2_to_f2(v.y);
                    float2 e2 = h2_to_f2(v.z);
                    float2 e3 = h2_to_f2(v.w);
                    a0 += w * e0.x; a1 += w * e0.y;
                    a2 += w * e1.x; a3 += w * e1.y;
                    a4 += w * e2.x; a5 += w * e2.y;
                    a6 += w * e3.x; a7 += w * e3.y;
                }
            }
            float d = a0 * p0.x + a1 * p0.y + a2 * p0.z + a3 * p0.w
                    + a4 * p1.x + a5 * p1.y + a6 * p1.z + a7 * p1.w;
            #pragma unroll
            for (int off = 16; off > 0; off >>= 1)
                d += __shfl_xor_sync(0xffffffffu, d, off);
            sc = d * (1.f / 16.f);
        }
        score[c] = sc;
        s[c][0] = a0; s[c][1] = a1; s[c][2] = a2; s[c][3] = a3;
        s[c][4] = a4; s[c][5] = a5; s[c][6] = a6; s[c][7] = a7;
    }

    float out[8];
    #pragma unroll
    for (int j = 0; j < 8; j++) out[j] = 0.f;
    float sumattn = 0.f;

    if (validbits) {
        float m = -1e30f;
        #pragma unroll
        for (int c = 0; c < CH; c++) m = fmaxf(m, score[c]);
        float wv[CH];
        float wsum = 0.f;
        #pragma unroll
        for (int c = 0; c < CH; c++) {
            float e = ((validbits >> c) & 1u) ? expf(score[c] - m) : 0.f;
            wv[c] = e;
            wsum += e;
        }
        float inv = 1.f / wsum;
        #pragma unroll
        for (int c = 0; c < CH; c++) {
            float a = wv[c] * inv;
            #pragma unroll
            for (int j = 0; j < 8; j++) out[j] += a * s[c][j];
        }
        sumattn = 1.f;
    }

    float4* srow = reinterpret_cast<float4*>(g_sbar + (size_t)token * DIM);
    srow[2 * lane]     = make_float4(to_tf32(out[0]), to_tf32(out[1]),
                                     to_tf32(out[2]), to_tf32(out[3]));
    srow[2 * lane + 1] = make_float4(to_tf32(out[4]), to_tf32(out[5]),
                                     to_tf32(out[6]), to_tf32(out[7]));
    if (lane == 0) g_sumattn[token] = sumattn;
}

// ---------------- launch -----------------------------------------------------
extern "C" void kernel_launch(void* const* d_in, const int* in_sizes, int n_in,
                              void* d_out, int out_size) {
    const float* queries = (const float*)d_in[0];
    const float* feat    = (const float*)d_in[1];
    const float* coords  = (const float*)d_in[2];
    const int*   vmask   = (const int*)d_in[3];
    const float* Wq      = (const float*)d_in[4];
    const float* bq      = (const float*)d_in[5];
    const float* Wkv     = (const float*)d_in[6];
    const float* bkv     = (const float*)d_in[7];
    const float* Wo      = (const float*)d_in[8];
    const float* bo      = (const float*)d_in[9];
    const float* gamma   = (const float*)d_in[10];
    const float* beta    = (const float*)d_in[11];
    float* out = (float*)d_out;

    precompute_AB_kernel<<<dim3(4, 4, 2), 256>>>(Wq, Wkv, Wo);
    precompute_vec_kernel<<<1, 256>>>(bq, Wkv, bkv, Wo);
    convert_feat_kernel<<<FEAT_U4 / 256, 256>>>(feat);
    ln_kernel<<<TOKENS / 8, 256>>>(queries, gamma, beta);

    gemm_tf32_kernel<1><<<dim3(TOKENS / 128, DIM / 64), 256>>>(nullptr, nullptr, nullptr);

    sample_attn_kernel<<<TOKENS / 8, 256>>>(coords, vmask);

    gemm_tf32_kernel<2><<<dim3(TOKENS / 128, DIM / 64), 256>>>(out, bo, queries);
}

// round 7
// speedup vs baseline: 1.5916x; 1.3584x over previous
#include <cuda_runtime.h>
#include <cuda_fp16.h>
#include <math.h>
#include <stdint.h>

// Problem constants (B, C, N, D, H, W) = (2, 8, 16384, 256, 64, 64)
#define BATCH 2
#define CH 8
#define NTOK 16384
#define DIM 256
#define IMH 64
#define IMW 64
#define TOKENS (BATCH * NTOK)                    // 32768
#define FEAT_U4 (BATCH * CH * IMH * IMW * 32)    // uint4 count (8 fp16 each)
#define CONV_BLOCKS (FEAT_U4 / 256)              // 8192
#define LN_BLOCKS (TOKENS / 8)                   // 4096

// ---------------- scratch (device globals; no runtime allocation) ----------
__device__ float g_qn[TOKENS * DIM];      // LN output, tf32-rounded
__device__ float g_P[TOKENS * DIM];       // p = qn @ A + cA
__device__ float g_sbar[TOKENS * DIM];    // attn-weighted sampled feats, tf32-rounded
__device__ float g_sumattn[TOKENS];       // 1.0 if any channel valid else 0.0
__device__ float g_A[DIM * DIM];          // tf32-rounded
__device__ float g_B2[DIM * DIM];         // tf32-rounded
__device__ float g_cA[DIM];
__device__ float g_bvWo[DIM];
__device__ uint4 g_featu4[FEAT_U4];       // image features packed as fp16 (8 per uint4)

// ---------------- helpers ---------------------------------------------------
__device__ __forceinline__ float to_tf32(float x) {
    uint32_t u;
    asm("cvt.rna.tf32.f32 %0, %1;" : "=r"(u) : "f"(x));
    return __uint_as_float(u);
}

__device__ __forceinline__ void mma_tf32(float c[4], const float a[4], const float b[2]) {
    const uint32_t* A = reinterpret_cast<const uint32_t*>(a);
    const uint32_t* B = reinterpret_cast<const uint32_t*>(b);
    asm volatile(
        "mma.sync.aligned.m16n8k8.row.col.f32.tf32.tf32.f32 "
        "{%0,%1,%2,%3}, {%4,%5,%6,%7}, {%8,%9}, {%0,%1,%2,%3};\n"
        : "+f"(c[0]), "+f"(c[1]), "+f"(c[2]), "+f"(c[3])
        : "r"(A[0]), "r"(A[1]), "r"(A[2]), "r"(A[3]),
          "r"(B[0]), "r"(B[1]));
}

__device__ __forceinline__ void cp_async16(void* smem, const void* gmem) {
    uint32_t s = (uint32_t)__cvta_generic_to_shared(smem);
    asm volatile("cp.async.ca.shared.global [%0], [%1], 16;\n" :: "r"(s), "l"(gmem));
}
__device__ __forceinline__ void cp_commit() {
    asm volatile("cp.async.commit_group;\n");
}
template <int N>
__device__ __forceinline__ void cp_wait() {
    asm volatile("cp.async.wait_group %0;\n" :: "n"(N));
}

__device__ __forceinline__ float2 h2_to_f2(uint32_t u) {
    __half2 h = *reinterpret_cast<__half2*>(&u);
    return __half22float2(h);
}
__device__ __forceinline__ uint32_t pack_h2(float x, float y) {
    __half2 h = __floats2half2_rn(x, y);
    return *reinterpret_cast<uint32_t*>(&h);
}

// ---------------- K1: precompute A, B2, cA, bvWo (single launch) -------------
// z in {0,1}: tiled GEMM for A / B2. z==2, block(0,0): vector precompute.
__global__ __launch_bounds__(256) void precomp_all_kernel(const float* __restrict__ Wq,
                                                          const float* __restrict__ Wkv,
                                                          const float* __restrict__ Wo,
                                                          const float* __restrict__ bq,
                                                          const float* __restrict__ bkv) {
    int z = blockIdx.z;
    int tid = threadIdx.x;

    if (z == 2) {
        if (blockIdx.x != 0 || blockIdx.y != 0) return;
        int lane = tid & 31, warp = tid >> 5;
        float4 q0 = *reinterpret_cast<const float4*>(bq + lane * 8);
        float4 q1 = *reinterpret_cast<const float4*>(bq + lane * 8 + 4);
        for (int i = warp; i < DIM; i += 8) {
            float4 w0 = *reinterpret_cast<const float4*>(Wkv + (size_t)i * 2 * DIM + lane * 8);
            float4 w1 = *reinterpret_cast<const float4*>(Wkv + (size_t)i * 2 * DIM + lane * 8 + 4);
            float s = w0.x * q0.x + w0.y * q0.y + w0.z * q0.z + w0.w * q0.w
                    + w1.x * q1.x + w1.y * q1.y + w1.z * q1.z + w1.w * q1.w;
            #pragma unroll
            for (int off = 16; off > 0; off >>= 1)
                s += __shfl_xor_sync(0xffffffffu, s, off);
            if (lane == 0) g_cA[i] = s;
        }
        float t = 0.f;
        for (int d = 0; d < DIM; d++)
            t += bkv[DIM + d] * Wo[d * DIM + tid];
        g_bvWo[tid] = t;
        return;
    }

    __shared__ float UT[64][68];
    __shared__ float VT[64][68];
    int r0 = blockIdx.y * 64;
    int c0 = blockIdx.x * 64;
    int tr = tid >> 4, tc = tid & 15;

    float acc[4][4];
    #pragma unroll
    for (int i = 0; i < 4; i++)
        #pragma unroll
        for (int j = 0; j < 4; j++) acc[i][j] = 0.f;

    for (int kc = 0; kc < DIM; kc += 64) {
        #pragma unroll
        for (int t = tid; t < 1024; t += 256) {
            int row = t >> 4;
            int col = (t & 15) * 4;
            float4 u, v;
            if (z == 0) {
                u = *reinterpret_cast<const float4*>(Wq + (r0 + row) * DIM + kc + col);
                v = *reinterpret_cast<const float4*>(Wkv + (c0 + row) * 2 * DIM + kc + col);
                VT[col + 0][row] = v.x;
                VT[col + 1][row] = v.y;
                VT[col + 2][row] = v.z;
                VT[col + 3][row] = v.w;
            } else {
                u = *reinterpret_cast<const float4*>(Wkv + (r0 + row) * 2 * DIM + DIM + kc + col);
                v = *reinterpret_cast<const float4*>(Wo + (kc + row) * DIM + c0 + col);
                VT[row][col + 0] = v.x;
                VT[row][col + 1] = v.y;
                VT[row][col + 2] = v.z;
                VT[row][col + 3] = v.w;
            }
            UT[col + 0][row] = u.x;
            UT[col + 1][row] = u.y;
            UT[col + 2][row] = u.z;
            UT[col + 3][row] = u.w;
        }
        __syncthreads();
        #pragma unroll 8
        for (int k = 0; k < 64; k++) {
            float4 a = *reinterpret_cast<float4*>(&UT[k][tr * 4]);
            float4 b = *reinterpret_cast<float4*>(&VT[k][tc * 4]);
            float av[4] = {a.x, a.y, a.z, a.w};
            float bv[4] = {b.x, b.y, b.z, b.w};
            #pragma unroll
            for (int i = 0; i < 4; i++)
                #pragma unroll
                for (int j = 0; j < 4; j++) acc[i][j] += av[i] * bv[j];
        }
        __syncthreads();
    }

    float* Outm = z ? g_B2 : g_A;
    #pragma unroll
    for (int i = 0; i < 4; i++) {
        float4 o = make_float4(to_tf32(acc[i][0]), to_tf32(acc[i][1]),
                               to_tf32(acc[i][2]), to_tf32(acc[i][3]));
        *reinterpret_cast<float4*>(Outm + (size_t)(r0 + tr * 4 + i) * DIM + c0 + tc * 4) = o;
    }
}

// ---------------- K2: convert features to fp16 + LayerNorm (single launch) ---
__global__ __launch_bounds__(256) void convert_ln_kernel(const float* __restrict__ feat,
                                                         const float* __restrict__ q,
                                                         const float* __restrict__ gamma,
                                                         const float* __restrict__ beta) {
    if (blockIdx.x < CONV_BLOCKS) {
        int i = blockIdx.x * 256 + threadIdx.x;
        const float4* f4 = reinterpret_cast<const float4*>(feat);
        float4 a = f4[2 * i];
        float4 b = f4[2 * i + 1];
        uint4 o;
        o.x = pack_h2(a.x, a.y);
        o.y = pack_h2(a.z, a.w);
        o.z = pack_h2(b.x, b.y);
        o.w = pack_h2(b.z, b.w);
        g_featu4[i] = o;
        return;
    }

    int token = (blockIdx.x - CONV_BLOCKS) * 8 + (threadIdx.x >> 5);
    int lane = threadIdx.x & 31;
    const float4* row = reinterpret_cast<const float4*>(q + (size_t)token * DIM);
    float4 x0 = row[lane];
    float4 x1 = row[lane + 32];

    float sum = x0.x + x0.y + x0.z + x0.w + x1.x + x1.y + x1.z + x1.w;
    float sq  = x0.x * x0.x + x0.y * x0.y + x0.z * x0.z + x0.w * x0.w
              + x1.x * x1.x + x1.y * x1.y + x1.z * x1.z + x1.w * x1.w;
    #pragma unroll
    for (int off = 16; off > 0; off >>= 1) {
        sum += __shfl_xor_sync(0xffffffffu, sum, off);
        sq  += __shfl_xor_sync(0xffffffffu, sq, off);
    }
    float mu = sum * (1.f / DIM);
    float var = sq * (1.f / DIM) - mu * mu;
    float rstd = rsqrtf(var + 1e-5f);

    const float4* g4 = reinterpret_cast<const float4*>(gamma);
    const float4* b4 = reinterpret_cast<const float4*>(beta);
    float4 ga = g4[lane], gb = g4[lane + 32];
    float4 ba = b4[lane], bb = b4[lane + 32];

    float4 o0, o1;
    o0.x = to_tf32((x0.x - mu) * rstd * ga.x + ba.x);
    o0.y = to_tf32((x0.y - mu) * rstd * ga.y + ba.y);
    o0.z = to_tf32((x0.z - mu) * rstd * ga.z + ba.z);
    o0.w = to_tf32((x0.w - mu) * rstd * ga.w + ba.w);
    o1.x = to_tf32((x1.x - mu) * rstd * gb.x + bb.x);
    o1.y = to_tf32((x1.y - mu) * rstd * gb.y + bb.y);
    o1.z = to_tf32((x1.z - mu) * rstd * gb.z + bb.z);
    o1.w = to_tf32((x1.w - mu) * rstd * gb.w + bb.w);

    float4* orow = reinterpret_cast<float4*>(g_qn + (size_t)token * DIM);
    orow[lane] = o0;
    orow[lane + 32] = o1;
}

// ---------------- tf32 GEMM with cp.async double buffering -------------------
// MODE 1:  g_P  = g_qn  @ g_A  + cA
// MODE 2:  Out  = resid + g_sbar @ g_B2 + sumattn*bvWo + bo
template <int MODE>
__global__ __launch_bounds__(256) void gemm_tf32_kernel(float* __restrict__ OutParam,
                                                        const float* __restrict__ bo,
                                                        const float* __restrict__ resid) {
    const float* Ain = (MODE == 1) ? g_qn : g_sbar;
    const float* Wm  = (MODE == 1) ? g_A : g_B2;
    float* Out = (MODE == 1) ? g_P : OutParam;

    __shared__ float As[2][128 * 36];
    __shared__ float Bs[2][32 * 72];

    int tid = threadIdx.x;
    int warp = tid >> 5, lane = tid & 31;
    int wm = warp >> 1, wn = warp & 1;
    int grp = lane >> 2, tig = lane & 3;
    int m0 = blockIdx.x * 128;
    int n0 = blockIdx.y * 64;

    int ar = tid >> 3;
    int ac = (tid & 7) * 4;
    int bk = tid >> 4;
    int bn = (tid & 15) * 4;

    float acc[2][4][4];
    #pragma unroll
    for (int mt = 0; mt < 2; mt++)
        #pragma unroll
        for (int nt = 0; nt < 4; nt++)
            #pragma unroll
            for (int i = 0; i < 4; i++) acc[mt][nt][i] = 0.f;

    auto stage = [&](int kc, int buf) {
        #pragma unroll
        for (int rr = 0; rr < 4; rr++) {
            int row = ar + rr * 32;
            cp_async16(&As[buf][row * 36 + ac],
                       Ain + (size_t)(m0 + row) * DIM + kc + ac);
        }
        #pragma unroll
        for (int kk = 0; kk < 2; kk++) {
            int krow = bk + kk * 16;
            cp_async16(&Bs[buf][krow * 72 + bn],
                       Wm + (size_t)(kc + krow) * DIM + n0 + bn);
        }
        cp_commit();
    };

    stage(0, 0);

    #pragma unroll 1
    for (int c = 0; c < 8; c++) {
        int buf = c & 1;
        if (c < 7) stage((c + 1) * 32, buf ^ 1);
        if (c < 7) cp_wait<1>(); else cp_wait<0>();
        __syncthreads();

        #pragma unroll
        for (int ks = 0; ks < 4; ks++) {
            int k8 = ks * 8;
            float a[2][4], bf[4][2];
            #pragma unroll
            for (int mt = 0; mt < 2; mt++) {
                int row = wm * 32 + mt * 16 + grp;
                a[mt][0] = As[buf][row * 36 + k8 + tig];
                a[mt][1] = As[buf][(row + 8) * 36 + k8 + tig];
                a[mt][2] = As[buf][row * 36 + k8 + tig + 4];
                a[mt][3] = As[buf][(row + 8) * 36 + k8 + tig + 4];
            }
            #pragma unroll
            for (int nt = 0; nt < 4; nt++) {
                int col = wn * 32 + nt * 8 + grp;
                bf[nt][0] = Bs[buf][(k8 + tig) * 72 + col];
                bf[nt][1] = Bs[buf][(k8 + tig + 4) * 72 + col];
            }
            #pragma unroll
            for (int mt = 0; mt < 2; mt++)
                #pragma unroll
                for (int nt = 0; nt < 4; nt++)
                    mma_tf32(acc[mt][nt], a[mt], bf[nt]);
        }
        __syncthreads();
    }

    #pragma unroll
    for (int mt = 0; mt < 2; mt++) {
        #pragma unroll
        for (int nt = 0; nt < 4; nt++) {
            #pragma unroll
            for (int half = 0; half < 2; half++) {
                int r = m0 + wm * 32 + mt * 16 + grp + half * 8;
                int col = n0 + wn * 32 + nt * 8 + tig * 2;
                float v0 = acc[mt][nt][half * 2 + 0];
                float v1 = acc[mt][nt][half * 2 + 1];
                if (MODE == 1) {
                    v0 += g_cA[col];
                    v1 += g_cA[col + 1];
                } else {
                    float sa = g_sumattn[r];
                    v0 += resid[(size_t)r * DIM + col]     + sa * g_bvWo[col]     + bo[col];
                    v1 += resid[(size_t)r * DIM + col + 1] + sa * g_bvWo[col + 1] + bo[col + 1];
                }
                *reinterpret_cast<float2*>(Out + (size_t)r * DIM + col) =
                    make_float2(v0, v1);
            }
        }
    }
}

// ---------------- K4: bilinear sample + ONLINE softmax + sbar ----------------
// One warp per token. s_c consumed immediately by online-softmax accumulation:
// no s[CH][8] register array -> ~45 regs -> high occupancy hides shfl chains.
__global__ __launch_bounds__(256) void sample_attn_kernel(const float* __restrict__ coords,
                                                          const int* __restrict__ vmask) {
    int token = blockIdx.x * 8 + (threadIdx.x >> 5);
    int lane = threadIdx.x & 31;
    int b = token >> 14;
    int n = token & (NTOK - 1);

    const float4* prow = reinterpret_cast<const float4*>(g_P + (size_t)token * DIM);
    float4 p0 = prow[2 * lane];       // dims [8*lane, 8*lane+4)
    float4 p1 = prow[2 * lane + 1];   // dims [8*lane+4, 8*lane+8)

    float m = -1e30f;   // running max
    float l = 0.f;      // running sum of exp
    float o0 = 0.f, o1 = 0.f, o2 = 0.f, o3 = 0.f;
    float o4 = 0.f, o5 = 0.f, o6 = 0.f, o7 = 0.f;

    #pragma unroll
    for (int c = 0; c < CH; c++) {
        int bc = b * CH + c;
        if (!vmask[bc * NTOK + n]) continue;   // warp-uniform

        float2 xy = *reinterpret_cast<const float2*>(
            coords + ((size_t)bc * NTOK + n) * 2);
        float x = (xy.x + 1.f) * 0.5f * (float)(IMW - 1);
        float y = (xy.y + 1.f) * 0.5f * (float)(IMH - 1);
        float x0f = floorf(x), y0f = floorf(y);
        int x0 = (int)x0f, y0 = (int)y0f;
        float wx1 = x - x0f, wy1 = y - y0f;
        float ws[4] = {(1.f - wy1) * (1.f - wx1), (1.f - wy1) * wx1,
                       wy1 * (1.f - wx1),          wy1 * wx1};
        int xs[4] = {x0, x0 + 1, x0, x0 + 1};
        int ys[4] = {y0, y0, y0 + 1, y0 + 1};

        float s0 = 0.f, s1 = 0.f, s2 = 0.f, s3 = 0.f;
        float s4 = 0.f, s5 = 0.f, s6 = 0.f, s7 = 0.f;
        const uint4* fb = g_featu4 + (size_t)bc * (IMH * IMW * 32);
        #pragma unroll
        for (int k = 0; k < 4; k++) {
            float w = ws[k];
            int xx = xs[k], yy = ys[k];
            if (w != 0.f && xx >= 0 && xx < IMW && yy >= 0 && yy < IMH) {
                uint4 v = fb[(yy * IMW + xx) * 32 + lane];
                float2 e0 = h2_to_f2(v.x);
                float2 e1 = h2_to_f2(v.y);
                float2 e2 = h2_to_f2(v.z);
                float2 e3 = h2_to_f2(v.w);
                s0 += w * e0.x; s1 += w * e0.y;
                s2 += w * e1.x; s3 += w * e1.y;
                s4 += w * e2.x; s5 += w * e2.y;
                s6 += w * e3.x; s7 += w * e3.y;
            }
        }
        float d = s0 * p0.x + s1 * p0.y + s2 * p0.z + s3 * p0.w
                + s4 * p1.x + s5 * p1.y + s6 * p1.z + s7 * p1.w;
        #pragma unroll
        for (int off = 16; off > 0; off >>= 1)
            d += __shfl_xor_sync(0xffffffffu, d, off);
        float score = d * (1.f / 16.f);   // 1/sqrt(256)

        // online softmax update
        float m_new = fmaxf(m, score);
        float f = __expf(m - m_new);      // 0 when m was -inf-ish
        float e = __expf(score - m_new);
        l = l * f + e;
        o0 = o0 * f + e * s0;
        o1 = o1 * f + e * s1;
        o2 = o2 * f + e * s2;
        o3 = o3 * f + e * s3;
        o4 = o4 * f + e * s4;
        o5 = o5 * f + e * s5;
        o6 = o6 * f + e * s6;
        o7 = o7 * f + e * s7;
        m = m_new;
    }

    float inv = (l > 0.f) ? (1.f / l) : 0.f;
    float4* srow = reinterpret_cast<float4*>(g_sbar + (size_t)token * DIM);
    srow[2 * lane]     = make_float4(to_tf32(o0 * inv), to_tf32(o1 * inv),
                                     to_tf32(o2 * inv), to_tf32(o3 * inv));
    srow[2 * lane + 1] = make_float4(to_tf32(o4 * inv), to_tf32(o5 * inv),
                                     to_tf32(o6 * inv), to_tf32(o7 * inv));
    if (lane == 0) g_sumattn[token] = (l > 0.f) ? 1.f : 0.f;
}

// ---------------- launch -----------------------------------------------------
extern "C" void kernel_launch(void* const* d_in, const int* in_sizes, int n_in,
                              void* d_out, int out_size) {
    const float* queries = (const float*)d_in[0];
    const float* feat    = (const float*)d_in[1];
    const float* coords  = (const float*)d_in[2];
    const int*   vmask   = (const int*)d_in[3];
    const float* Wq      = (const float*)d_in[4];
    const float* bq      = (const float*)d_in[5];
    const float* Wkv     = (const float*)d_in[6];
    const float* bkv     = (const float*)d_in[7];
    const float* Wo      = (const float*)d_in[8];
    const float* bo      = (const float*)d_in[9];
    const float* gamma   = (const float*)d_in[10];
    const float* beta    = (const float*)d_in[11];
    float* out = (float*)d_out;

    // Launch order keeps the sampler at profiled slot #4.
    precomp_all_kernel<<<dim3(4, 4, 3), 256>>>(Wq, Wkv, Wo, bq, bkv);
    convert_ln_kernel<<<CONV_BLOCKS + LN_BLOCKS, 256>>>(feat, queries, gamma, beta);
    gemm_tf32_kernel<1><<<dim3(TOKENS / 128, DIM / 64), 256>>>(nullptr, nullptr, nullptr);
    sample_attn_kernel<<<TOKENS / 8, 256>>>(coords, vmask);
    gemm_tf32_kernel<2><<<dim3(TOKENS / 128, DIM / 64), 256>>>(out, bo, queries);
}